// round 16
// baseline (speedup 1.0000x reference)
#include <cuda_runtime.h>
#include <cuda_bf16.h>
#include <math.h>
#include <stdint.h>

#define E_DIM 512
#define BLROWS 16384
#define NRR 100
#define NCS 128                         // 16 n-tiles of 8 (tiles 12.. partial/phantom)
#define NORM_TERM 10.82490511970208f    // ln(50257)
#define LOG_NR 4.605170185988092f       // ln(100)
#define MROWS 32                        // rows per CTA
#define ASTR 144                        // bf16 A-tile row stride (72 bf16)
#define ASTAGE (MROWS * ASTR)           // 4608
#define GBYTES (MROWS * 2048)           // 65536: FULL per-CTA gather (f32)
#define NBLK 512

// B fragment table: [kstep(32)][grp(4)][pair(2)][lane(32)] x uint4
// uint4 = {t0.b0,t0.b1,t1.b0,t1.b1}, tiles t0=grp*4+pair*2, t1=t0+1 (0..15).
// n >= 100 entries are zero (phantom); epilogue cs=-1e30 makes them no-ops.
__device__ __align__(16) uint4 g_bf4[32 * 4 * 2 * 32];   // 131072 B
__device__ float g_part[NBLK];
__device__ int   g_ctr = 0;             // self-resetting (graph-replay safe)

__device__ __forceinline__ uint32_t smem_u32(const void* p) {
    uint32_t a;
    asm("{ .reg .u64 t; cvta.to.shared.u64 t, %1; cvt.u32.u64 %0, t; }" : "=r"(a) : "l"(p));
    return a;
}
__device__ __forceinline__ void cp_async16(uint32_t dst, const void* src) {
    asm volatile("cp.async.cg.shared.global [%0], [%1], 16;" :: "r"(dst), "l"(src) : "memory");
}
#define CP_COMMIT() asm volatile("cp.async.commit_group;" ::: "memory")
#define CP_WAITN(n) asm volatile("cp.async.wait_group %0;" :: "n"(n) : "memory")
__device__ __forceinline__ void ldmatrix_x4(uint32_t& r0, uint32_t& r1,
                                            uint32_t& r2, uint32_t& r3, uint32_t addr) {
    asm volatile("ldmatrix.sync.aligned.m8n8.x4.shared.b16 {%0,%1,%2,%3}, [%4];"
                 : "=r"(r0), "=r"(r1), "=r"(r2), "=r"(r3) : "r"(addr));
}
__device__ __forceinline__ void mma16816(float* d, const uint32_t* a,
                                         uint32_t b0, uint32_t b1) {
    asm volatile("mma.sync.aligned.m16n8k16.row.col.f32.bf16.bf16.f32 "
                 "{%0,%1,%2,%3}, {%4,%5,%6,%7}, {%8,%9}, {%0,%1,%2,%3};"
                 : "+f"(d[0]), "+f"(d[1]), "+f"(d[2]), "+f"(d[3])
                 : "r"(a[0]), "r"(a[1]), "r"(a[2]), "r"(a[3]), "r"(b0), "r"(b1));
}
__device__ __forceinline__ float softplus_exact(float x) {
    return fmaxf(x, 0.0f) + log1pf(expf(-fabsf(x)));
}
__device__ __forceinline__ uint2 cvt_bf16x4(float4 v) {
    __nv_bfloat162 p0 = __float22bfloat162_rn(make_float2(v.x, v.y));
    __nv_bfloat162 p1 = __float22bfloat162_rn(make_float2(v.z, v.w));
    uint2 r;
    r.x = *reinterpret_cast<uint32_t*>(&p0);
    r.y = *reinterpret_cast<uint32_t*>(&p1);
    return r;
}

// ---------------------------------------------------------------------------
// Prep: build the B fragment table (one u32 per thread, 32768 total).
// ---------------------------------------------------------------------------
__global__ void prep_kernel(const float* __restrict__ emb,
                            const int* __restrict__ nidx) {
    int u = blockIdx.x * blockDim.x + threadIdx.x;
    if (u >= 32768) return;
    int comp = u & 3;                   // {t0.b0, t0.b1, t1.b0, t1.b1}
    int e = u >> 2;
    int lane = e & 31;
    int pair = (e >> 5) & 1;
    int grp  = (e >> 6) & 3;
    int s    = e >> 8;                  // kstep 0..31
    int tile = grp * 4 + pair * 2 + (comp >> 1);
    uint32_t val = 0;
    int n = tile * 8 + (lane >> 2);
    if (n < NRR) {
        int k = s * 16 + (lane & 3) * 2 + (comp & 1) * 8;
        const float* src = emb + (size_t)nidx[n] * E_DIM + k;
        __nv_bfloat162 pk = __float22bfloat162_rn(make_float2(src[0], src[1]));
        val = *reinterpret_cast<uint32_t*>(&pk);
    }
    reinterpret_cast<uint32_t*>(g_bf4)[e * 4 + comp] = val;
}

// ---------------------------------------------------------------------------
// Main: 32-row CTAs, 256 thr, 3/SM. FULL gather (64KB) cp.async'd at CTA
// start in 8 chunk-ordered groups; loop waits wait_group(7-c) only. Input via
// register-prefetch LDG (2-iter cover); B from L2-hot fragment table; A
// f32->bf16 into 2-stage smem ring; one __syncthreads per chunk.
// Warp w: M-slab w&1 (16 rows), n-group w>>1 (4 tiles = 32 cols).
// ---------------------------------------------------------------------------
__global__ void __launch_bounds__(256, 3)
mega_kernel(const float* __restrict__ inp,
            const float* __restrict__ emb,
            const float* __restrict__ bias,
            const float* __restrict__ lpn,
            const int*   __restrict__ tgt,
            const int*   __restrict__ nidx,
            float* __restrict__ out) {
    extern __shared__ char dsm[];
    __shared__ float cs[NCS];
    __shared__ int   s_t[MROWS];
    __shared__ float s_xc[MROWS];
    __shared__ float s_tdot[MROWS];
    __shared__ float s_red[4][MROWS];
    __shared__ float s_fin[MROWS];
    __shared__ int   s_flag;

    const int tid = threadIdx.x;
    const int lane = tid & 31;
    const int warp = tid >> 5;
    const int row0 = blockIdx.x * MROWS;

    const uint32_t db = smem_u32(dsm);
    const uint32_t abase = (db + 127u) & ~127u;
    const uint32_t gbase = abase + 2 * ASTAGE;
    char* ap = dsm + (abase - db);
    char* gp = dsm + (gbase - db);

    if (tid < NCS) {
        int nv = (tid < NRR) ? nidx[tid] : -1;
        cs[tid] = (tid < NRR) ? (bias[nv] - NORM_TERM - lpn[nv] - LOG_NR) : -1e30f;
    }
    if (tid >= 128 && tid < 128 + MROWS) {
        int r = tid - 128;
        int t = tgt[row0 + r];
        s_t[r] = t;
        s_xc[r] = bias[t] - NORM_TERM - lpn[t] - LOG_NR;
    }
    __syncthreads();

    // ---------------- per-thread layout ----------------
    const int l4 = tid & 15;            // 16B k-slot
    const int rg = tid >> 4;            // 0..15; rows rg, rg+16
    const float* ipt = inp + (size_t)(row0 + rg) * E_DIM + l4 * 4;
    const char* embB = (const char*)emb;
    const uint32_t gsrc0 = (uint32_t)s_t[rg] * 2048u + (uint32_t)l4 * 16u;
    const uint32_t gsrc1 = (uint32_t)s_t[rg + 16] * 2048u + (uint32_t)l4 * 16u;
    const uint32_t gdst0 = (uint32_t)rg * 2048u + (uint32_t)l4 * 16u;
    const uint32_t gdst1 = gdst0 + 16u * 2048u;

    // ---- PROLOGUE: issue the ENTIRE gather as 8 chunk-ordered groups ----
#pragma unroll
    for (int c = 0; c < 8; c++) {
        cp_async16(gbase + gdst0 + c * 256, embB + gsrc0 + c * 256);
        cp_async16(gbase + gdst1 + c * 256, embB + gsrc1 + c * 256);
        CP_COMMIT();
    }

    // input prefetch (chunks 0,1)
    float4 va[2][2];
#pragma unroll
    for (int s = 0; s < 2; s++) {
        va[s][0] = *(const float4*)(ipt + s * 64);
        va[s][1] = *(const float4*)(ipt + s * 64 + 16 * E_DIM);
    }

    // MMA fragment addressing
    const int m0 = (warp & 1) * 16;
    const int grp = warp >> 1;          // 0..3, 4 tiles each
    const uint32_t a_woff = (uint32_t)(m0 + (lane & 15)) * ASTR + ((lane >> 4) << 4);
    const uint4* btw = g_bf4 + (size_t)grp * 64 + lane;   // + s*256, pair at +32

    float acc[4][4];
#pragma unroll
    for (int n = 0; n < 4; n++)
#pragma unroll
        for (int j = 0; j < 4; j++) acc[n][j] = 0.f;
    float tacc0 = 0.f, tacc1 = 0.f;

    // ---------------- main loop: 8 chunks, ONE sync each ----------------
#pragma unroll
    for (int c = 0; c < 8; c++) {
        const int set = c & 1;
        // gather chunk c resident?  groups complete in order.
        if      (c == 0) CP_WAITN(7);
        else if (c == 1) CP_WAITN(6);
        else if (c == 2) CP_WAITN(5);
        else if (c == 3) CP_WAITN(4);
        else if (c == 4) CP_WAITN(3);
        else if (c == 5) CP_WAITN(2);
        else if (c == 6) CP_WAITN(1);
        else             CP_WAITN(0);
        // dot (smem gather x input regs) + convert + STS A(c) into stage c&1
        {
            char* adst = ap + set * ASTAGE + rg * ASTR + l4 * 8;
            const char* gsp = gp + rg * 2048 + c * 256 + l4 * 16;
            float4 v0 = va[set][0], v1 = va[set][1];
            float4 g0 = *(const float4*)(gsp);
            float4 g1 = *(const float4*)(gsp + 16 * 2048);
            tacc0 += v0.x * g0.x + v0.y * g0.y + v0.z * g0.z + v0.w * g0.w;
            tacc1 += v1.x * g1.x + v1.y * g1.y + v1.z * g1.z + v1.w * g1.w;
            *(uint2*)(adst) = cvt_bf16x4(v0);
            *(uint2*)(adst + 16 * ASTR) = cvt_bf16x4(v1);
        }
        if (c < 6) {                    // input LDG chunk c+2 (2-iter cover)
            const int ko = (c + 2) * 64;
            va[set][0] = *(const float4*)(ipt + ko);
            va[set][1] = *(const float4*)(ipt + ko + 16 * E_DIM);
        }
        __syncthreads();                // A(c) visible; MMA(c-1) done by all
        // MMA chunk c: A smem stage c&1, B from L2-hot fragment table
        {
            const uint32_t ab = abase + set * ASTAGE + a_woff;
#pragma unroll
            for (int k0 = 0; k0 < 4; k0++) {
                uint32_t a[4];
                ldmatrix_x4(a[0], a[1], a[2], a[3], ab + k0 * 32);
                const uint4* bt = btw + (size_t)(c * 4 + k0) * 256;
                uint4 q0 = bt[0];
                uint4 q1 = bt[32];
                mma16816(acc[0], a, q0.x, q0.y);
                mma16816(acc[1], a, q0.z, q0.w);
                mma16816(acc[2], a, q1.x, q1.y);
                mma16816(acc[3], a, q1.z, q1.w);
            }
        }
    }

    // --- finish exact target dots (reduce over the 16 k-slot lanes) ---
    {
        float v0 = tacc0, v1 = tacc1;
#pragma unroll
        for (int off = 8; off > 0; off >>= 1) {
            v0 += __shfl_xor_sync(0xFFFFFFFFu, v0, off);
            v1 += __shfl_xor_sync(0xFFFFFFFFu, v1, off);
        }
        if (l4 == 0) {
            s_tdot[rg] = v0;
            s_tdot[rg + 16] = v1;
        }
    }

    // --- softplus epilogue (product trick; noise x <= -1.8; phantoms no-op) ---
    {
        const int g = lane >> 2;
        const int tq = lane & 3;
        float plo = 1.f, phi = 1.f;
#pragma unroll
        for (int nt = 0; nt < 4; nt++) {
            float c0 = cs[grp * 32 + nt * 8 + 2 * tq];
            float c1 = cs[grp * 32 + nt * 8 + 2 * tq + 1];
            plo *= (1.f + __expf(acc[nt][0] + c0));
            plo *= (1.f + __expf(acc[nt][1] + c1));
            phi *= (1.f + __expf(acc[nt][2] + c0));
            phi *= (1.f + __expf(acc[nt][3] + c1));
        }
        float slo = __logf(plo);
        float shi = __logf(phi);
        slo += __shfl_xor_sync(0xFFFFFFFFu, slo, 1);
        slo += __shfl_xor_sync(0xFFFFFFFFu, slo, 2);
        shi += __shfl_xor_sync(0xFFFFFFFFu, shi, 1);
        shi += __shfl_xor_sync(0xFFFFFFFFu, shi, 2);
        if (tq == 0) {
            s_red[grp][m0 + g] = slo;
            s_red[grp][m0 + g + 8] = shi;
        }
    }
    __syncthreads();

    // --- per-row combine (+ target slot), block + grid reduce ---
    if (tid < MROWS) {
        float x0 = s_tdot[tid] + s_xc[tid];
        s_fin[tid] = s_red[0][tid] + s_red[1][tid] + s_red[2][tid] + s_red[3][tid]
                   + softplus_exact(x0) - x0;
    }
    __syncthreads();
    if (tid < 32) {
        float s = s_fin[tid];
        s += __shfl_xor_sync(0xFFFFFFFFu, s, 16);
        s += __shfl_xor_sync(0xFFFFFFFFu, s, 8);
        s += __shfl_xor_sync(0xFFFFFFFFu, s, 4);
        s += __shfl_xor_sync(0xFFFFFFFFu, s, 2);
        s += __shfl_xor_sync(0xFFFFFFFFu, s, 1);
        if (lane == 0) {
            g_part[blockIdx.x] = s;
            __threadfence();
            int old = atomicAdd(&g_ctr, 1);
            s_flag = (old == NBLK - 1);
        }
        __syncwarp();
        if (s_flag) {
            __threadfence();
            float t = 0.f;
#pragma unroll
            for (int k = 0; k < NBLK / 32; k++)
                t += *((volatile float*)&g_part[lane + 32 * k]);
            t += __shfl_xor_sync(0xFFFFFFFFu, t, 16);
            t += __shfl_xor_sync(0xFFFFFFFFu, t, 8);
            t += __shfl_xor_sync(0xFFFFFFFFu, t, 4);
            t += __shfl_xor_sync(0xFFFFFFFFu, t, 2);
            t += __shfl_xor_sync(0xFFFFFFFFu, t, 1);
            if (lane == 0) {
                out[0] = t * (1.0f / (float)BLROWS);
                g_ctr = 0;
            }
        }
    }
}

// ---------------------------------------------------------------------------
extern "C" void kernel_launch(void* const* d_in, const int* in_sizes, int n_in,
                              void* d_out, int out_size) {
    const float* inp  = (const float*)d_in[0];
    const float* emb  = (const float*)d_in[1];
    const float* bias = (const float*)d_in[2];
    const float* lpn  = (const float*)d_in[3];
    const int*   tgt  = (const int*)  d_in[4];
    const int*   nidx = (const int*)  d_in[5];
    float* out = (float*)d_out;

    const int DSM = 128 + 2 * ASTAGE + GBYTES;   // 74880 B -> 3 CTAs/SM by smem
    cudaFuncSetAttribute(mega_kernel, cudaFuncAttributeMaxDynamicSharedMemorySize, DSM);

    prep_kernel<<<128, 256>>>(emb, nidx);
    mega_kernel<<<NBLK, 256, DSM>>>(inp, emb, bias, lpn, tgt, nidx, out);
}

// round 17
// speedup vs baseline: 1.1732x; 1.1732x over previous
#include <cuda_runtime.h>
#include <cuda_bf16.h>
#include <math.h>
#include <stdint.h>

#define E_DIM 512
#define BLROWS 16384
#define NRR 100
#define NCS 128
#define NORM_TERM 10.82490511970208f    // ln(50257)
#define LOG_NR 4.605170185988092f       // ln(100)
#define MROWS 32                        // rows per CTA
#define ASTR 144                        // bf16 A row stride
#define ACH 4608                        // A chunk: 32 rows x 144B
#define GSTR 2064                       // f32 gather row stride (4-way bank max)
#define GBYTES (MROWS * GSTR)           // 66048
#define NBLK 512

// B fragment table: [kstep(32)][grp(4)][pair(2)][lane(32)] x uint4  (proven R16)
__device__ __align__(16) uint4 g_bf4[32 * 4 * 2 * 32];   // 131072 B
__device__ float g_part[NBLK];
__device__ int   g_ctr = 0;

__device__ __forceinline__ uint32_t smem_u32(const void* p) {
    uint32_t a;
    asm("{ .reg .u64 t; cvta.to.shared.u64 t, %1; cvt.u32.u64 %0, t; }" : "=r"(a) : "l"(p));
    return a;
}
#define MB_INIT(addr, cnt) \
    asm volatile("mbarrier.init.shared.b64 [%0], %1;" :: "r"(addr), "r"(cnt) : "memory")
#define MB_EXPECT_TX(addr, bytes) \
    asm volatile("mbarrier.arrive.expect_tx.shared.b64 _, [%0], %1;" :: "r"(addr), "r"(bytes) : "memory")
#define MB_WAIT(addr, par) do {                                                     \
    uint32_t _m = (addr), _p = (par), _d;                                           \
    asm volatile("{ .reg .pred p; mbarrier.try_wait.parity.acquire.cta.shared::cta.b64 p, [%1], %2; selp.b32 %0,1,0,p; }" \
        : "=r"(_d) : "r"(_m), "r"(_p) : "memory");                                  \
    if (!_d) {                                                                      \
        asm volatile("{ .reg .pred P1; WL_%=: mbarrier.try_wait.parity.acquire.cta.shared::cta.b64 P1, [%0], %1, 0x989680; @P1 bra.uni WD_%=; bra.uni WL_%=; WD_%=: }" \
            :: "r"(_m), "r"(_p) : "memory");                                        \
    } } while (0)
__device__ __forceinline__ void bulk_copy(uint32_t dst, const void* src,
                                          uint32_t bytes, uint32_t mbar) {
    asm volatile("cp.async.bulk.shared::cluster.global.mbarrier::complete_tx::bytes "
                 "[%0], [%1], %2, [%3];"
                 :: "r"(dst), "l"(src), "r"(bytes), "r"(mbar) : "memory");
}
__device__ __forceinline__ void ldmatrix_x4(uint32_t& r0, uint32_t& r1,
                                            uint32_t& r2, uint32_t& r3, uint32_t addr) {
    asm volatile("ldmatrix.sync.aligned.m8n8.x4.shared.b16 {%0,%1,%2,%3}, [%4];"
                 : "=r"(r0), "=r"(r1), "=r"(r2), "=r"(r3) : "r"(addr));
}
__device__ __forceinline__ void mma16816(float* d, const uint32_t* a,
                                         uint32_t b0, uint32_t b1) {
    asm volatile("mma.sync.aligned.m16n8k16.row.col.f32.bf16.bf16.f32 "
                 "{%0,%1,%2,%3}, {%4,%5,%6,%7}, {%8,%9}, {%0,%1,%2,%3};"
                 : "+f"(d[0]), "+f"(d[1]), "+f"(d[2]), "+f"(d[3])
                 : "r"(a[0]), "r"(a[1]), "r"(a[2]), "r"(a[3]), "r"(b0), "r"(b1));
}
__device__ __forceinline__ float softplus_exact(float x) {
    return fmaxf(x, 0.0f) + log1pf(expf(-fabsf(x)));
}
__device__ __forceinline__ uint2 cvt_bf16x4(float4 v) {
    __nv_bfloat162 p0 = __float22bfloat162_rn(make_float2(v.x, v.y));
    __nv_bfloat162 p1 = __float22bfloat162_rn(make_float2(v.z, v.w));
    uint2 r;
    r.x = *reinterpret_cast<uint32_t*>(&p0);
    r.y = *reinterpret_cast<uint32_t*>(&p1);
    return r;
}

// ---------------------------------------------------------------------------
// Prep: B fragment table (unchanged from R16 — proven).
// ---------------------------------------------------------------------------
__global__ void prep_kernel(const float* __restrict__ emb,
                            const int* __restrict__ nidx) {
    int u = blockIdx.x * blockDim.x + threadIdx.x;
    if (u >= 32768) return;
    int comp = u & 3;
    int e = u >> 2;
    int lane = e & 31;
    int pair = (e >> 5) & 1;
    int grp  = (e >> 6) & 3;
    int s    = e >> 8;
    int tile = grp * 4 + pair * 2 + (comp >> 1);
    uint32_t val = 0;
    int n = tile * 8 + (lane >> 2);
    if (n < NRR) {
        int k = s * 16 + (lane & 3) * 2 + (comp & 1) * 8;
        const float* src = emb + (size_t)nidx[n] * E_DIM + k;
        __nv_bfloat162 pk = __float22bfloat162_rn(make_float2(src[0], src[1]));
        val = *reinterpret_cast<uint32_t*>(&pk);
    }
    reinterpret_cast<uint32_t*>(g_bf4)[e * 4 + comp] = val;
}

// ---------------------------------------------------------------------------
// Phase-decoupled mega kernel. 32-row CTAs, 256 thr, 2/SM, grid 512.
//  P0: issue 32 bulk-copy gathers (engine-driven, mbarrier completion)
//  P1: stream input (16 LDG.128/thread, MLP 8) -> bf16 A smem, ZERO syncs
//  [one __syncthreads]
//  P2: pure MMA sweep (A smem x B fragment table), no stalls
//  P3: mbarrier wait -> target dot (bf16 A smem x f32 gather smem)
//  epilogue: softplus + fused grid reduce
// ---------------------------------------------------------------------------
__global__ void __launch_bounds__(256, 2)
mega_kernel(const float* __restrict__ inp,
            const float* __restrict__ emb,
            const float* __restrict__ bias,
            const float* __restrict__ lpn,
            const int*   __restrict__ tgt,
            const int*   __restrict__ nidx,
            float* __restrict__ out) {
    extern __shared__ char dsm[];
    __shared__ float cs[NCS];
    __shared__ int   s_t[MROWS];
    __shared__ float s_xc[MROWS];
    __shared__ float s_tp[8][MROWS];
    __shared__ float s_red[4][MROWS];
    __shared__ int   s_flag;
    __shared__ __align__(8) unsigned long long s_mbar;

    const int tid = threadIdx.x;
    const int lane = tid & 31;
    const int warp = tid >> 5;
    const int row0 = blockIdx.x * MROWS;

    const uint32_t db = smem_u32(dsm);
    const uint32_t abase = (db + 127u) & ~127u;
    const uint32_t gbase = abase + 8 * ACH;
    char* ap = dsm + (abase - db);
    char* gp = dsm + (gbase - db);

    if (tid < NCS) {
        int nv = (tid < NRR) ? nidx[tid] : -1;
        cs[tid] = (tid < NRR) ? (bias[nv] - NORM_TERM - lpn[nv] - LOG_NR) : -1e30f;
    }
    if (tid >= 64 && tid < 64 + MROWS) {
        int r = tid - 64;
        int t = tgt[row0 + r];
        s_t[r] = t;
        s_xc[r] = bias[t] - NORM_TERM - lpn[t] - LOG_NR;
    }
    if (tid == 0) MB_INIT(smem_u32(&s_mbar), 1);
    __syncthreads();
    const uint32_t mbar = smem_u32(&s_mbar);

    // ---- P0: issue entire gather as 32 bulk copies (warp 0) ----
    if (warp == 0) {
        if (lane == 0) MB_EXPECT_TX(mbar, (uint32_t)(MROWS * 2048));
        __syncwarp();
        bulk_copy(gbase + (uint32_t)lane * GSTR,
                  (const char*)emb + (size_t)s_t[lane] * 2048, 2048, mbar);
    }

    // ---- P1: stream input -> bf16 A smem (no syncs) ----
    const int l4 = tid & 15;
    const int rg = tid >> 4;            // rows rg, rg+16
    const float* ipt = inp + (size_t)(row0 + rg) * E_DIM + l4 * 4;
    const uint32_t asts = (uint32_t)rg * ASTR + l4 * 8;
#pragma unroll
    for (int b = 0; b < 2; b++) {
        float4 v[4][2];
#pragma unroll
        for (int c4 = 0; c4 < 4; c4++) {
            int c = b * 4 + c4;
            v[c4][0] = *(const float4*)(ipt + c * 64);
            v[c4][1] = *(const float4*)(ipt + c * 64 + 16 * E_DIM);
        }
#pragma unroll
        for (int c4 = 0; c4 < 4; c4++) {
            int c = b * 4 + c4;
            char* adst = ap + c * ACH + asts;
            *(uint2*)(adst) = cvt_bf16x4(v[c4][0]);
            *(uint2*)(adst + 16 * ASTR) = cvt_bf16x4(v[c4][1]);
        }
    }
    __syncthreads();                    // all A chunks visible

    // ---- P2: pure MMA sweep ----
    const int m0 = (warp & 1) * 16;
    const int grp = warp >> 1;
    const uint32_t a_woff = abase + (uint32_t)(m0 + (lane & 15)) * ASTR + ((lane >> 4) << 4);
    const uint4* btw = g_bf4 + (size_t)grp * 64 + lane;

    float acc[4][4];
#pragma unroll
    for (int n = 0; n < 4; n++)
#pragma unroll
        for (int j = 0; j < 4; j++) acc[n][j] = 0.f;

#pragma unroll
    for (int c = 0; c < 8; c++) {
        const uint32_t ab = a_woff + c * ACH;
#pragma unroll
        for (int k0 = 0; k0 < 4; k0++) {
            uint32_t a[4];
            ldmatrix_x4(a[0], a[1], a[2], a[3], ab + k0 * 32);
            const uint4* bt = btw + (size_t)(c * 4 + k0) * 256;
            uint4 q0 = bt[0];
            uint4 q1 = bt[32];
            mma16816(acc[0], a, q0.x, q0.y);
            mma16816(acc[1], a, q0.z, q0.w);
            mma16816(acc[2], a, q1.x, q1.y);
            mma16816(acc[3], a, q1.z, q1.w);
        }
    }

    // ---- P3: gather landed? target dot from bf16 A smem x f32 G smem ----
    MB_WAIT(mbar, 0);
    {
        const int row = tid & 31;
        const int seg = tid >> 5;       // k chunk 0..7
        const char* arow = ap + seg * ACH + row * ASTR;
        const char* grow = gp + row * GSTR + seg * 256;
        float d = 0.f;
#pragma unroll
        for (int i = 0; i < 8; i++) {
            uint4 au = *(const uint4*)(arow + i * 16);     // 8 bf16
            float4 g0 = *(const float4*)(grow + i * 32);
            float4 g1 = *(const float4*)(grow + i * 32 + 16);
            d += __uint_as_float(au.x << 16) * g0.x
               + __uint_as_float(au.x & 0xFFFF0000u) * g0.y
               + __uint_as_float(au.y << 16) * g0.z
               + __uint_as_float(au.y & 0xFFFF0000u) * g0.w
               + __uint_as_float(au.z << 16) * g1.x
               + __uint_as_float(au.z & 0xFFFF0000u) * g1.y
               + __uint_as_float(au.w << 16) * g1.z
               + __uint_as_float(au.w & 0xFFFF0000u) * g1.w;
        }
        s_tp[seg][row] = d;
    }

    // ---- softplus epilogue (product trick; phantoms cs=-1e30 -> no-op) ----
    {
        const int g = lane >> 2;
        const int tq = lane & 3;
        float plo = 1.f, phi = 1.f;
#pragma unroll
        for (int nt = 0; nt < 4; nt++) {
            float c0 = cs[grp * 32 + nt * 8 + 2 * tq];
            float c1 = cs[grp * 32 + nt * 8 + 2 * tq + 1];
            plo *= (1.f + __expf(acc[nt][0] + c0));
            plo *= (1.f + __expf(acc[nt][1] + c1));
            phi *= (1.f + __expf(acc[nt][2] + c0));
            phi *= (1.f + __expf(acc[nt][3] + c1));
        }
        float slo = __logf(plo);
        float shi = __logf(phi);
        slo += __shfl_xor_sync(0xFFFFFFFFu, slo, 1);
        slo += __shfl_xor_sync(0xFFFFFFFFu, slo, 2);
        shi += __shfl_xor_sync(0xFFFFFFFFu, shi, 1);
        shi += __shfl_xor_sync(0xFFFFFFFFu, shi, 2);
        if (tq == 0) {
            s_red[grp][m0 + g] = slo;
            s_red[grp][m0 + g + 8] = shi;
        }
    }
    __syncthreads();

    // ---- per-row combine, block + grid reduce ----
    if (tid < 32) {
        float td = 0.f;
#pragma unroll
        for (int sgm = 0; sgm < 8; sgm++) td += s_tp[sgm][tid];
        float x0 = td + s_xc[tid];
        float s = s_red[0][tid] + s_red[1][tid] + s_red[2][tid] + s_red[3][tid]
                + softplus_exact(x0) - x0;
        s += __shfl_xor_sync(0xFFFFFFFFu, s, 16);
        s += __shfl_xor_sync(0xFFFFFFFFu, s, 8);
        s += __shfl_xor_sync(0xFFFFFFFFu, s, 4);
        s += __shfl_xor_sync(0xFFFFFFFFu, s, 2);
        s += __shfl_xor_sync(0xFFFFFFFFu, s, 1);
        if (lane == 0) {
            g_part[blockIdx.x] = s;
            __threadfence();
            int old = atomicAdd(&g_ctr, 1);
            s_flag = (old == NBLK - 1);
        }
        __syncwarp();
        if (s_flag) {
            __threadfence();
            float t = 0.f;
#pragma unroll
            for (int k = 0; k < NBLK / 32; k++)
                t += *((volatile float*)&g_part[lane + 32 * k]);
            t += __shfl_xor_sync(0xFFFFFFFFu, t, 16);
            t += __shfl_xor_sync(0xFFFFFFFFu, t, 8);
            t += __shfl_xor_sync(0xFFFFFFFFu, t, 4);
            t += __shfl_xor_sync(0xFFFFFFFFu, t, 2);
            t += __shfl_xor_sync(0xFFFFFFFFu, t, 1);
            if (lane == 0) {
                out[0] = t * (1.0f / (float)BLROWS);
                g_ctr = 0;
            }
        }
    }
}

// ---------------------------------------------------------------------------
extern "C" void kernel_launch(void* const* d_in, const int* in_sizes, int n_in,
                              void* d_out, int out_size) {
    const float* inp  = (const float*)d_in[0];
    const float* emb  = (const float*)d_in[1];
    const float* bias = (const float*)d_in[2];
    const float* lpn  = (const float*)d_in[3];
    const int*   tgt  = (const int*)  d_in[4];
    const int*   nidx = (const int*)  d_in[5];
    float* out = (float*)d_out;

    const int DSM = 128 + 8 * ACH + GBYTES;   // 103040 B -> 2 CTAs/SM
    cudaFuncSetAttribute(mega_kernel, cudaFuncAttributeMaxDynamicSharedMemorySize, DSM);

    prep_kernel<<<128, 256>>>(emb, nidx);
    mega_kernel<<<NBLK, 256, DSM>>>(inp, emb, bias, lpn, tgt, nidx, out);
}